// round 14
// baseline (speedup 1.0000x reference)
#include <cuda_runtime.h>
#include <cuda_bf16.h>
#include <math.h>
#include <stdint.h>

#define B_   8
#define PLEN 2048
#define QLEN 1024
#define HID  1024

typedef __nv_bfloat16 bf16;

// Scratch planes (__device__ globals: allocation-free rule)
__device__ bf16 g_kh [(size_t)B_ * PLEN * HID];
__device__ bf16 g_kl [(size_t)B_ * PLEN * HID];
__device__ bf16 g_qh [(size_t)B_ * QLEN * HID];
__device__ bf16 g_ql [(size_t)B_ * QLEN * HID];
__device__ bf16 g_qTh[(size_t)B_ * HID * QLEN];
__device__ bf16 g_qTl[(size_t)B_ * HID * QLEN];
__device__ bf16 g_Wkh[(size_t)HID * HID];
__device__ bf16 g_Wkl[(size_t)HID * HID];
__device__ bf16 g_Wqh[(size_t)HID * HID];
__device__ bf16 g_Wql[(size_t)HID * HID];
__device__ bf16 g_pkh[(size_t)B_ * PLEN * HID];
__device__ bf16 g_pkl[(size_t)B_ * PLEN * HID];
__device__ bf16 g_qkh[(size_t)B_ * QLEN * HID];
__device__ bf16 g_qkl[(size_t)B_ * QLEN * HID];
__device__ bf16 g_ah [(size_t)B_ * PLEN * QLEN];
__device__ bf16 g_al [(size_t)B_ * PLEN * QLEN];

// ---------------------------------------------------------------------------
// helpers
// ---------------------------------------------------------------------------
__device__ __forceinline__ uint32_t smem_u32(const void* p) {
    return (uint32_t)__cvta_generic_to_shared(p);
}

// split two fp32 into packed bf16x2 (hi plane, lo plane); element0 in low half
__device__ __forceinline__ void split2(float x0, float x1,
                                       uint32_t& hi, uint32_t& lo) {
    uint32_t h;
    asm("cvt.rn.bf16x2.f32 %0, %1, %2;" : "=r"(h) : "f"(x1), "f"(x0));
    float h0 = __uint_as_float(h << 16);
    float h1 = __uint_as_float(h & 0xffff0000u);
    uint32_t l;
    asm("cvt.rn.bf16x2.f32 %0, %1, %2;" : "=r"(l) : "f"(x1 - h1), "f"(x0 - h0));
    hi = h; lo = l;
}

__device__ __forceinline__ void ldsm_x4(uint32_t r[4], uint32_t addr) {
    asm volatile("ldmatrix.sync.aligned.m8n8.x4.shared.b16 {%0,%1,%2,%3}, [%4];"
                 : "=r"(r[0]), "=r"(r[1]), "=r"(r[2]), "=r"(r[3]) : "r"(addr));
}

__device__ __forceinline__ void mma_bf16(float c[4], const uint32_t a[4],
                                         uint32_t b0, uint32_t b1) {
    asm volatile(
        "mma.sync.aligned.m16n8k16.row.col.f32.bf16.bf16.f32 "
        "{%0,%1,%2,%3}, {%4,%5,%6,%7}, {%8,%9}, {%0,%1,%2,%3};"
        : "+f"(c[0]), "+f"(c[1]), "+f"(c[2]), "+f"(c[3])
        : "r"(a[0]), "r"(a[1]), "r"(a[2]), "r"(a[3]), "r"(b0), "r"(b1));
}

__device__ __forceinline__ void cp16(uint32_t saddr, const void* g) {
    asm volatile("cp.async.cg.shared.global [%0], [%1], 16;"
                 :: "r"(saddr), "l"(g) : "memory");
}
#define CP_COMMIT() asm volatile("cp.async.commit_group;" ::: "memory")
#define CP_WAIT0()  asm volatile("cp.async.wait_group 0;" ::: "memory")

// ---------------------------------------------------------------------------
// 3xBF16 NT GEMM on pre-split planes, cp.async self-copy (no producer warps).
// C[m,n] = (opt relu) sum_k A[m,k]*B[n,k]; A/B given as bf16 hi/lo planes.
// CTA tile 128x128, BK=64, two-stage smem pipeline, 256 threads = 8 consumer
// warps (2Mx4N grid, 64x32 warp tile). Per chunk: 16 cp.async per thread,
// one wait_group + one __syncthreads.
// Output: fp32 C, or bf16 hi/lo planes Ch/Cl (out_planes).
// ---------------------------------------------------------------------------
#define STRD   144      // bytes per smem row: 64 bf16 (128B) + 16B pad
#define PLANE  18432    // 128 rows * 144
#define OFF_AH 0
#define OFF_AL PLANE
#define OFF_BH (2 * PLANE)
#define OFF_BL (3 * PLANE)
#define STAGE  (4 * PLANE)      // 73728
#define GSMEM  (2 * STAGE)      // 147456

__global__ __launch_bounds__(256, 1) void gemm_planes(
    const bf16* __restrict__ Ah, const bf16* __restrict__ Al,
    const bf16* __restrict__ Bh, const bf16* __restrict__ Bl,
    float* __restrict__ C, bf16* __restrict__ Ch, bf16* __restrict__ Cl,
    int K, int ldc, int relu, int out_planes,
    size_t sA, size_t sB, size_t sC)
{
    extern __shared__ __align__(128) char smem[];
    const uint32_t sbase = smem_u32(smem);
    const int tid  = threadIdx.x;
    const int lane = tid & 31;
    const int wid  = tid >> 5;
    const int m0 = blockIdx.y * 128;
    const int n0 = blockIdx.x * 128;
    const size_t zb = blockIdx.z;
    const char* pAh = (const char*)(Ah + zb * sA);
    const char* pAl = (const char*)(Al + zb * sA);
    const char* pBh = (const char*)(Bh + zb * sB);
    const char* pBl = (const char*)(Bl + zb * sB);

    // copy indexing: 4 planes x 128 rows x 8 segs(16B) = 4096 segs;
    // each thread: 4 segs per plane (idx = tid + 256*i)
    uint32_t sofs[4], gAo[4], gBo[4];
    #pragma unroll
    for (int i = 0; i < 4; i++) {
        int idx = tid + 256 * i;
        int row = idx >> 3, sg = idx & 7;
        sofs[i] = (uint32_t)(row * STRD + sg * 16);
        gAo[i]  = (uint32_t)(((m0 + row) * K + sg * 8) * 2);
        gBo[i]  = (uint32_t)(((n0 + row) * K + sg * 8) * 2);
    }

    auto COPY = [&](int s, int c) {
        const uint32_t kb = (uint32_t)c * 128u;   // 64 bf16 = 128 bytes
        const uint32_t st = sbase + s * STAGE;
        #pragma unroll
        for (int i = 0; i < 4; i++) {
            cp16(st + OFF_AH + sofs[i], pAh + gAo[i] + kb);
            cp16(st + OFF_AL + sofs[i], pAl + gAo[i] + kb);
            cp16(st + OFF_BH + sofs[i], pBh + gBo[i] + kb);
            cp16(st + OFF_BL + sofs[i], pBl + gBo[i] + kb);
        }
        CP_COMMIT();
    };

    // consumer indexing: warp grid 2(M) x 4(N); warp tile 64x32
    const int wm = (wid & 1) * 64;
    const int wn = (wid >> 1) * 32;
    const int a_row = (lane & 15);
    const int a_kc  = (lane >> 4) * 8;
    const int b_row = ((lane >> 4) << 3) + (lane & 7);
    const int b_kc  = ((lane >> 3) & 1) * 8;

    float acc[4][4][4] = {};   // [mt][nb*2+nt][frag]

    const int nCh = K / 64;
    COPY(0, 0);

    #pragma unroll 1
    for (int c = 0; c < nCh; ++c) {
        CP_WAIT0();
        __syncthreads();           // stage (c&1) visible to all; prior reads done
        if (c + 1 < nCh) COPY((c + 1) & 1, c + 1);

        const uint32_t stb = sbase + (c & 1) * STAGE;
        #pragma unroll
        for (int kk = 0; kk < 64; kk += 16) {
            uint32_t ah[4][4], al[4][4], bh[2][4], bl[2][4];
            #pragma unroll
            for (int mt = 0; mt < 4; mt++) {
                uint32_t ro = (uint32_t)((wm + mt * 16 + a_row) * STRD +
                                         (kk + a_kc) * 2);
                ldsm_x4(ah[mt], stb + OFF_AH + ro);
                ldsm_x4(al[mt], stb + OFF_AL + ro);
            }
            #pragma unroll
            for (int nb = 0; nb < 2; nb++) {
                uint32_t ro = (uint32_t)((wn + nb * 16 + b_row) * STRD +
                                         (kk + b_kc) * 2);
                ldsm_x4(bh[nb], stb + OFF_BH + ro);
                ldsm_x4(bl[nb], stb + OFF_BL + ro);
            }
            // pass 1: hi*hi — 16 independent MMAs
            #pragma unroll
            for (int mt = 0; mt < 4; mt++)
                #pragma unroll
                for (int nb = 0; nb < 2; nb++)
                    #pragma unroll
                    for (int nt = 0; nt < 2; nt++)
                        mma_bf16(acc[mt][nb * 2 + nt], ah[mt],
                                 bh[nb][nt * 2], bh[nb][nt * 2 + 1]);
            // pass 2: hi*lo
            #pragma unroll
            for (int mt = 0; mt < 4; mt++)
                #pragma unroll
                for (int nb = 0; nb < 2; nb++)
                    #pragma unroll
                    for (int nt = 0; nt < 2; nt++)
                        mma_bf16(acc[mt][nb * 2 + nt], ah[mt],
                                 bl[nb][nt * 2], bl[nb][nt * 2 + 1]);
            // pass 3: lo*hi
            #pragma unroll
            for (int mt = 0; mt < 4; mt++)
                #pragma unroll
                for (int nb = 0; nb < 2; nb++)
                    #pragma unroll
                    for (int nt = 0; nt < 2; nt++)
                        mma_bf16(acc[mt][nb * 2 + nt], al[mt],
                                 bh[nb][nt * 2], bh[nb][nt * 2 + 1]);
        }
        __syncthreads();           // all reads of this stage done before refill
    }

    // epilogue
    const int g = lane >> 2, cc2 = (lane & 3) * 2;
    #pragma unroll
    for (int mt = 0; mt < 4; mt++) {
        #pragma unroll
        for (int j = 0; j < 4; j++) {
            int row = m0 + wm + mt * 16 + g;
            int col = n0 + wn + j * 8 + cc2;
            float* a4 = acc[mt][j];
            if (relu) {
                a4[0] = fmaxf(a4[0], 0.f); a4[1] = fmaxf(a4[1], 0.f);
                a4[2] = fmaxf(a4[2], 0.f); a4[3] = fmaxf(a4[3], 0.f);
            }
            if (out_planes) {
                bf16* ch = Ch + zb * sC;
                bf16* cl = Cl + zb * sC;
                uint32_t h0, l0, h1, l1;
                split2(a4[0], a4[1], h0, l0);
                split2(a4[2], a4[3], h1, l1);
                size_t o0 = ((size_t)row * ldc + col) * 2;
                size_t o1 = ((size_t)(row + 8) * ldc + col) * 2;
                *(uint32_t*)((char*)ch + o0) = h0;
                *(uint32_t*)((char*)cl + o0) = l0;
                *(uint32_t*)((char*)ch + o1) = h1;
                *(uint32_t*)((char*)cl + o1) = l1;
            } else {
                float* Cb = C + zb * sC;
                *(float2*)(Cb + (size_t)row * ldc + col) =
                    make_float2(a4[0], a4[1]);
                *(float2*)(Cb + (size_t)(row + 8) * ldc + col) =
                    make_float2(a4[2], a4[3]);
            }
        }
    }
}

// ---------------------------------------------------------------------------
// elementwise fp32 -> (hi, lo) bf16 planes
// ---------------------------------------------------------------------------
__global__ void split_mat(const float4* __restrict__ src,
                          uint2* __restrict__ dh, uint2* __restrict__ dl,
                          int n4)
{
    int i = blockIdx.x * blockDim.x + threadIdx.x;
    if (i >= n4) return;
    float4 v = src[i];
    uint2 h, l;
    split2(v.x, v.y, h.x, l.x);
    split2(v.z, v.w, h.y, l.y);
    dh[i] = h; dl[i] = l;
}

// ---------------------------------------------------------------------------
// q[b][j][h] (f32) -> qT planes [b][h][j] (bf16 hi/lo)
// ---------------------------------------------------------------------------
__global__ void transpose_qp(const float* __restrict__ q,
                             bf16* __restrict__ th, bf16* __restrict__ tl)
{
    __shared__ float tile[32][33];
    const int b = blockIdx.z;
    const int j0 = blockIdx.x * 32, h0 = blockIdx.y * 32;
    const float* qb = q + (size_t)b * QLEN * HID;
    bf16* thb = th + (size_t)b * HID * QLEN;
    bf16* tlb = tl + (size_t)b * HID * QLEN;
    const int tx = threadIdx.x, ty = threadIdx.y;
    #pragma unroll
    for (int r = ty; r < 32; r += 8)
        tile[r][tx] = qb[(size_t)(j0 + r) * HID + h0 + tx];
    __syncthreads();
    if (tx < 16) {
        #pragma unroll
        for (int r = ty; r < 32; r += 8) {
            uint32_t h, l;
            split2(tile[2 * tx][r], tile[2 * tx + 1][r], h, l);
            size_t o = ((size_t)(h0 + r) * QLEN + j0 + 2 * tx) * 2;
            *(uint32_t*)((char*)thb + o) = h;
            *(uint32_t*)((char*)tlb + o) = l;
        }
    }
}

// ---------------------------------------------------------------------------
// In-place row softmax over Q with q_mask; also emits alpha hi/lo planes.
// Each thread: 4 consecutive elements.
// ---------------------------------------------------------------------------
__global__ __launch_bounds__(256) void softmax_rows(
    float* __restrict__ sc, const unsigned char* __restrict__ qmask,
    bf16* __restrict__ ah, bf16* __restrict__ al)
{
    const int row = blockIdx.x;
    const int b   = row / PLEN;
    float* s = sc + (size_t)row * QLEN;
    const unsigned char* m = qmask + (size_t)b * QLEN;

    const int t = threadIdx.x;
    float4 x = *(const float4*)(s + t * 4);
    uchar4 mk = *(const uchar4*)(m + t * 4);
    float v[4] = {x.x, x.y, x.z, x.w};
    if (mk.x) v[0] = -INFINITY;
    if (mk.y) v[1] = -INFINITY;
    if (mk.z) v[2] = -INFINITY;
    if (mk.w) v[3] = -INFINITY;
    float mx = fmaxf(fmaxf(v[0], v[1]), fmaxf(v[2], v[3]));

    __shared__ float warpred[8];
    __shared__ float bcast;

    #pragma unroll
    for (int o = 16; o; o >>= 1) mx = fmaxf(mx, __shfl_xor_sync(0xffffffffu, mx, o));
    if ((t & 31) == 0) warpred[t >> 5] = mx;
    __syncthreads();
    if (t == 0) {
        float r = warpred[0];
        #pragma unroll
        for (int w = 1; w < 8; w++) r = fmaxf(r, warpred[w]);
        bcast = r;
    }
    __syncthreads();
    mx = bcast;

    float sum = 0.0f;
    #pragma unroll
    for (int i = 0; i < 4; i++) { v[i] = expf(v[i] - mx); sum += v[i]; }
    __syncthreads();

    #pragma unroll
    for (int o = 16; o; o >>= 1) sum += __shfl_xor_sync(0xffffffffu, sum, o);
    if ((t & 31) == 0) warpred[t >> 5] = sum;
    __syncthreads();
    if (t == 0) {
        float r = 0.0f;
        #pragma unroll
        for (int w = 0; w < 8; w++) r += warpred[w];
        bcast = r;
    }
    __syncthreads();
    const float inv = 1.0f / bcast;

    #pragma unroll
    for (int i = 0; i < 4; i++) v[i] *= inv;
    *(float4*)(s + t * 4) = make_float4(v[0], v[1], v[2], v[3]);

    uint2 h, l;
    split2(v[0], v[1], h.x, l.x);
    split2(v[2], v[3], h.y, l.y);
    ((uint2*)(ah + (size_t)row * QLEN))[t] = h;
    ((uint2*)(al + (size_t)row * QLEN))[t] = l;
}

// ---------------------------------------------------------------------------
extern "C" void kernel_launch(void* const* d_in, const int* in_sizes, int n_in,
                              void* d_out, int out_size)
{
    (void)in_sizes; (void)n_in; (void)out_size;
    const float*         k     = (const float*)d_in[0];          // [B, P, H]
    const float*         q     = (const float*)d_in[1];          // [B, Q, H]
    const unsigned char* qmask = (const unsigned char*)d_in[2];  // [B, Q] bool
    const float*         Wk    = (const float*)d_in[3];          // [H, H]
    const float*         Wq    = (const float*)d_in[4];          // [H, H]

    float* ctx    = (float*)d_out;                               // [B, P, H]
    float* alphas = ctx + (size_t)B_ * PLEN * HID;               // [B, P, Q]

    bf16 *kh, *kl, *qh, *ql, *qTh, *qTl, *Wkh, *Wkl, *Wqh, *Wql;
    bf16 *pkh, *pkl, *qkh, *qkl, *ah, *al;
    cudaGetSymbolAddress((void**)&kh,  g_kh);  cudaGetSymbolAddress((void**)&kl,  g_kl);
    cudaGetSymbolAddress((void**)&qh,  g_qh);  cudaGetSymbolAddress((void**)&ql,  g_ql);
    cudaGetSymbolAddress((void**)&qTh, g_qTh); cudaGetSymbolAddress((void**)&qTl, g_qTl);
    cudaGetSymbolAddress((void**)&Wkh, g_Wkh); cudaGetSymbolAddress((void**)&Wkl, g_Wkl);
    cudaGetSymbolAddress((void**)&Wqh, g_Wqh); cudaGetSymbolAddress((void**)&Wql, g_Wql);
    cudaGetSymbolAddress((void**)&pkh, g_pkh); cudaGetSymbolAddress((void**)&pkl, g_pkl);
    cudaGetSymbolAddress((void**)&qkh, g_qkh); cudaGetSymbolAddress((void**)&qkl, g_qkl);
    cudaGetSymbolAddress((void**)&ah,  g_ah);  cudaGetSymbolAddress((void**)&al,  g_al);

    static int smem_set = 0;
    if (!smem_set) {
        cudaFuncSetAttribute(gemm_planes,
                             cudaFuncAttributeMaxDynamicSharedMemorySize, GSMEM);
        smem_set = 1;
    }

    // preprocessing: split inputs into bf16 planes
    {
        int n4k = (B_ * PLEN * HID) / 4;
        split_mat<<<(n4k + 255) / 256, 256>>>((const float4*)k,
                                              (uint2*)kh, (uint2*)kl, n4k);
        int n4q = (B_ * QLEN * HID) / 4;
        split_mat<<<(n4q + 255) / 256, 256>>>((const float4*)q,
                                              (uint2*)qh, (uint2*)ql, n4q);
        int n4w = (HID * HID) / 4;
        split_mat<<<(n4w + 255) / 256, 256>>>((const float4*)Wk,
                                              (uint2*)Wkh, (uint2*)Wkl, n4w);
        split_mat<<<(n4w + 255) / 256, 256>>>((const float4*)Wq,
                                              (uint2*)Wqh, (uint2*)Wql, n4w);
        transpose_qp<<<dim3(QLEN / 32, HID / 32, B_), dim3(32, 8)>>>(q, qTh, qTl);
    }

    // 1) p_key planes = relu(k @ Wk^T)
    gemm_planes<<<dim3(HID / 128, (B_ * PLEN) / 128, 1), 256, GSMEM>>>(
        kh, kl, Wkh, Wkl, nullptr, pkh, pkl,
        HID, HID, 1, 1, 0, 0, 0);

    // 2) q_key planes = relu(q @ Wq^T)
    gemm_planes<<<dim3(HID / 128, (B_ * QLEN) / 128, 1), 256, GSMEM>>>(
        qh, ql, Wqh, Wql, nullptr, qkh, qkl,
        HID, HID, 1, 1, 0, 0, 0);

    // 3) scores[b] = p_key[b] @ q_key[b]^T  -> f32 into alphas region
    gemm_planes<<<dim3(QLEN / 128, PLEN / 128, B_), 256, GSMEM>>>(
        pkh, pkl, qkh, qkl, alphas, nullptr, nullptr,
        HID, QLEN, 0, 0,
        (size_t)PLEN * HID, (size_t)QLEN * HID, (size_t)PLEN * QLEN);

    // 4) softmax in place + alpha planes
    softmax_rows<<<B_ * PLEN, 256>>>(alphas, qmask, ah, al);

    // 5) ctx[b] = alphas[b] @ q[b] == alphas[b] @ (qT[b])^T  (NT)
    gemm_planes<<<dim3(HID / 128, PLEN / 128, B_), 256, GSMEM>>>(
        ah, al, qTh, qTl, ctx, nullptr, nullptr,
        QLEN, HID, 0, 0,
        (size_t)PLEN * QLEN, (size_t)HID * QLEN, (size_t)PLEN * HID);
}

// round 17
// speedup vs baseline: 1.0946x; 1.0946x over previous
#include <cuda_runtime.h>
#include <cuda_bf16.h>
#include <math.h>
#include <stdint.h>

#define B_   8
#define PLEN 2048
#define QLEN 1024
#define HID  1024

// Scratch (__device__ globals: allocation-free rule)
__device__ float g_pkey[(size_t)B_ * PLEN * HID];   // 64 MB
__device__ float g_qkey[(size_t)B_ * QLEN * HID];   // 32 MB
__device__ float g_qT  [(size_t)B_ * HID  * QLEN];  // 32 MB

// ---------------------------------------------------------------------------
// helpers
// ---------------------------------------------------------------------------
__device__ __forceinline__ uint32_t smem_u32(const void* p) {
    return (uint32_t)__cvta_generic_to_shared(p);
}

// split two fp32 into packed bf16x2 (hi plane, lo plane); element0 in low half
__device__ __forceinline__ void split2(float x0, float x1,
                                       uint32_t& hi, uint32_t& lo) {
    uint32_t h;
    asm("cvt.rn.bf16x2.f32 %0, %1, %2;" : "=r"(h) : "f"(x1), "f"(x0));
    float h0 = __uint_as_float(h << 16);           // bf16 -> f32 via shift
    float h1 = __uint_as_float(h & 0xffff0000u);
    uint32_t l;
    asm("cvt.rn.bf16x2.f32 %0, %1, %2;" : "=r"(l) : "f"(x1 - h1), "f"(x0 - h0));
    hi = h; lo = l;
}

__device__ __forceinline__ void ldsm_x4(uint32_t r[4], uint32_t addr) {
    asm volatile("ldmatrix.sync.aligned.m8n8.x4.shared.b16 {%0,%1,%2,%3}, [%4];"
                 : "=r"(r[0]), "=r"(r[1]), "=r"(r[2]), "=r"(r[3]) : "r"(addr));
}

__device__ __forceinline__ void mma_bf16(float c[4], const uint32_t a[4],
                                         uint32_t b0, uint32_t b1) {
    asm volatile(
        "mma.sync.aligned.m16n8k16.row.col.f32.bf16.bf16.f32 "
        "{%0,%1,%2,%3}, {%4,%5,%6,%7}, {%8,%9}, {%0,%1,%2,%3};"
        : "+f"(c[0]), "+f"(c[1]), "+f"(c[2]), "+f"(c[3])
        : "r"(a[0]), "r"(a[1]), "r"(a[2]), "r"(a[3]), "r"(b0), "r"(b1));
}

// ---------------------------------------------------------------------------
// 3xBF16 NT GEMM, warp-specialized, TWO CTAs per SM.
// C[m,n] = (opt relu) sum_k A[m,k]*B[n,k], fp32 in/out.
// CTA tile 128(M)x64(N), BK=64, two-stage split-bf16 smem pipeline.
// 192 threads: warps 0-3 consumers (2Mx2N grid, 64x32 warp tile);
// warps 4-5 producers (LDG -> split -> STS). One __syncthreads per chunk.
// Halved CTA lets 2 CTAs co-reside per SM: their chunk-boundary bubbles
// interleave instead of idling the tensor pipe.
// ---------------------------------------------------------------------------
#define STRD    144      // bytes per smem row: 64 bf16 (128B) + 16B pad
#define PLANE_A 18432    // 128 rows * 144
#define PLANE_B 9216     // 64 rows * 144
#define OFF_AH  0
#define OFF_AL  PLANE_A
#define OFF_BH  (2 * PLANE_A)
#define OFF_BL  (2 * PLANE_A + PLANE_B)
#define STAGE   (2 * PLANE_A + 2 * PLANE_B)   // 55296
#define GSMEM   (2 * STAGE)                   // 110592
#define NTHREADS 192

__global__ __launch_bounds__(NTHREADS, 2) void gemm_3xbf16(
    const float* __restrict__ A, const float* __restrict__ Bm,
    float* __restrict__ C, int K, int ldc, int relu,
    size_t sA, size_t sB, size_t sC)
{
    extern __shared__ __align__(128) char smem[];
    const uint32_t sbase = smem_u32(smem);
    const int tid  = threadIdx.x;
    const int lane = tid & 31;
    const int wid  = tid >> 5;
    const int m0 = blockIdx.y * 128;
    const int n0 = blockIdx.x * 64;
    A  += (size_t)blockIdx.z * sA;
    Bm += (size_t)blockIdx.z * sB;
    C  += (size_t)blockIdx.z * sC;

    const int nCh = K / 64;

    if (wid >= 4) {
        // ===================== PRODUCER (warps 4-5, 64 threads) ============
        const int pt = tid - 128;           // 0..63
        const int prow = pt >> 4;           // 0..3
        const int pc4  = pt & 15;           // 0..15 (float4 column)
        const char* Ab = (const char*)(A  + (size_t)(m0 + prow) * K + pc4 * 4);
        const char* Bb = (const char*)(Bm + (size_t)(n0 + prow) * K + pc4 * 4);
        const uint32_t rowK4 = (uint32_t)K * 4u;     // bytes per gmem row
        const uint32_t sts0  = (uint32_t)(prow * STRD + pc4 * 8);

        float4 buf[2][8];

        // A rounds r=0..3 cover rows 32r..32r+31; B rounds r=0..1 rows 32r..
        auto LDG_A = [&](int c, int r, int pb) {
            uint32_t kb = (uint32_t)c * 256u;
            #pragma unroll
            for (int j = 0; j < 8; j++)
                buf[pb][j] = *(const float4*)(Ab + (uint32_t)(32 * r + 4 * j) * rowK4 + kb);
        };
        auto LDG_B = [&](int c, int r, int pb) {
            uint32_t kb = (uint32_t)c * 256u;
            #pragma unroll
            for (int j = 0; j < 8; j++)
                buf[pb][j] = *(const float4*)(Bb + (uint32_t)(32 * r + 4 * j) * rowK4 + kb);
        };
        auto STS_A = [&](int s, int r, int pb) {
            char* st = smem + s * STAGE;
            #pragma unroll
            for (int j = 0; j < 8; j++) {
                uint32_t so = sts0 + (uint32_t)(32 * r + 4 * j) * STRD;
                uint2 h, l;
                split2(buf[pb][j].x, buf[pb][j].y, h.x, l.x);
                split2(buf[pb][j].z, buf[pb][j].w, h.y, l.y);
                *(uint2*)(st + OFF_AH + so) = h;
                *(uint2*)(st + OFF_AL + so) = l;
            }
        };
        auto STS_B = [&](int s, int r, int pb) {
            char* st = smem + s * STAGE;
            #pragma unroll
            for (int j = 0; j < 8; j++) {
                uint32_t so = sts0 + (uint32_t)(32 * r + 4 * j) * STRD;
                uint2 h, l;
                split2(buf[pb][j].x, buf[pb][j].y, h.x, l.x);
                split2(buf[pb][j].z, buf[pb][j].w, h.y, l.y);
                *(uint2*)(st + OFF_BH + so) = h;
                *(uint2*)(st + OFF_BL + so) = l;
            }
        };
        auto FILL = [&](int s, int c) {
            LDG_A(c, 0, 0); LDG_A(c, 1, 1);
            STS_A(s, 0, 0); LDG_A(c, 2, 0);
            STS_A(s, 1, 1); LDG_A(c, 3, 1);
            STS_A(s, 2, 0); LDG_B(c, 0, 0);
            STS_A(s, 3, 1); LDG_B(c, 1, 1);
            STS_B(s, 0, 0);
            STS_B(s, 1, 1);
        };

        FILL(0, 0);                         // prologue: chunk 0 -> stage 0
        __syncthreads();
        #pragma unroll 1
        for (int c = 0; c < nCh; ++c) {
            if (c + 1 < nCh) FILL((c + 1) & 1, c + 1);
            __syncthreads();
        }
        return;                              // producers done (no epilogue)
    }

    // ========================= CONSUMER (warps 0-3) ========================
    // warp grid: 2(M) x 2(N); warp tile 64x32
    const int wm = (wid & 1) * 64;
    const int wn = (wid >> 1) * 32;
    const int a_row = (lane & 15);
    const int a_kc  = (lane >> 4) * 8;
    const int b_row = ((lane >> 4) << 3) + (lane & 7);
    const int b_kc  = ((lane >> 3) & 1) * 8;

    float acc[4][4][4] = {};   // [mt][nb*2+nt][frag]

    __syncthreads();           // matches producer prologue barrier

    #pragma unroll 1
    for (int c = 0; c < nCh; ++c) {
        const uint32_t stb = sbase + (c & 1) * STAGE;
        #pragma unroll
        for (int kk = 0; kk < 64; kk += 16) {
            uint32_t ah[4][4], al[4][4], bh[2][4], bl[2][4];
            #pragma unroll
            for (int mt = 0; mt < 4; mt++) {
                uint32_t ro = (uint32_t)((wm + mt * 16 + a_row) * STRD +
                                         (kk + a_kc) * 2);
                ldsm_x4(ah[mt], stb + OFF_AH + ro);
                ldsm_x4(al[mt], stb + OFF_AL + ro);
            }
            #pragma unroll
            for (int nb = 0; nb < 2; nb++) {
                uint32_t ro = (uint32_t)((wn + nb * 16 + b_row) * STRD +
                                         (kk + b_kc) * 2);
                ldsm_x4(bh[nb], stb + OFF_BH + ro);
                ldsm_x4(bl[nb], stb + OFF_BL + ro);
            }
            // pass 1: hi*hi — 16 independent MMAs
            #pragma unroll
            for (int mt = 0; mt < 4; mt++)
                #pragma unroll
                for (int nb = 0; nb < 2; nb++)
                    #pragma unroll
                    for (int nt = 0; nt < 2; nt++)
                        mma_bf16(acc[mt][nb * 2 + nt], ah[mt],
                                 bh[nb][nt * 2], bh[nb][nt * 2 + 1]);
            // pass 2: hi*lo
            #pragma unroll
            for (int mt = 0; mt < 4; mt++)
                #pragma unroll
                for (int nb = 0; nb < 2; nb++)
                    #pragma unroll
                    for (int nt = 0; nt < 2; nt++)
                        mma_bf16(acc[mt][nb * 2 + nt], ah[mt],
                                 bl[nb][nt * 2], bl[nb][nt * 2 + 1]);
            // pass 3: lo*hi
            #pragma unroll
            for (int mt = 0; mt < 4; mt++)
                #pragma unroll
                for (int nb = 0; nb < 2; nb++)
                    #pragma unroll
                    for (int nt = 0; nt < 2; nt++)
                        mma_bf16(acc[mt][nb * 2 + nt], al[mt],
                                 bh[nb][nt * 2], bh[nb][nt * 2 + 1]);
        }
        __syncthreads();
    }

    // epilogue (consumers only)
    const int g = lane >> 2, cc2 = (lane & 3) * 2;
    #pragma unroll
    for (int mt = 0; mt < 4; mt++) {
        #pragma unroll
        for (int j = 0; j < 4; j++) {
            int row = m0 + wm + mt * 16 + g;
            int col = n0 + wn + j * 8 + cc2;
            float* a4 = acc[mt][j];
            if (relu) {
                a4[0] = fmaxf(a4[0], 0.f); a4[1] = fmaxf(a4[1], 0.f);
                a4[2] = fmaxf(a4[2], 0.f); a4[3] = fmaxf(a4[3], 0.f);
            }
            *(float2*)(C + (size_t)row * ldc + col)       = make_float2(a4[0], a4[1]);
            *(float2*)(C + (size_t)(row + 8) * ldc + col) = make_float2(a4[2], a4[3]);
        }
    }
}

// ---------------------------------------------------------------------------
// q[b][j][h] -> qT[b][h][j]
// ---------------------------------------------------------------------------
__global__ void transpose_q(const float* __restrict__ q, float* __restrict__ qT)
{
    __shared__ float tile[32][33];
    const int b = blockIdx.z;
    const int j0 = blockIdx.x * 32, h0 = blockIdx.y * 32;
    const float* qb = q + (size_t)b * QLEN * HID;
    float* tb = qT + (size_t)b * HID * QLEN;
    #pragma unroll
    for (int r = threadIdx.y; r < 32; r += 8)
        tile[r][threadIdx.x] = qb[(size_t)(j0 + r) * HID + h0 + threadIdx.x];
    __syncthreads();
    #pragma unroll
    for (int r = threadIdx.y; r < 32; r += 8)
        tb[(size_t)(h0 + r) * QLEN + j0 + threadIdx.x] = tile[threadIdx.x][r];
}

// ---------------------------------------------------------------------------
// In-place row softmax over Q with q_mask (True = pad -> -inf).
// ---------------------------------------------------------------------------
__global__ __launch_bounds__(256) void softmax_rows(
    float* __restrict__ sc, const unsigned char* __restrict__ qmask)
{
    const int row = blockIdx.x;
    const int b   = row / PLEN;
    float* s = sc + (size_t)row * QLEN;
    const unsigned char* m = qmask + (size_t)b * QLEN;

    const int t = threadIdx.x;
    float v[4];
    float mx = -INFINITY;
    #pragma unroll
    for (int i = 0; i < 4; i++) {
        int idx = t + i * 256;
        float x = s[idx];
        if (m[idx]) x = -INFINITY;
        v[i] = x;
        mx = fmaxf(mx, x);
    }

    __shared__ float warpred[8];
    __shared__ float bcast;

    #pragma unroll
    for (int o = 16; o; o >>= 1) mx = fmaxf(mx, __shfl_xor_sync(0xffffffffu, mx, o));
    if ((t & 31) == 0) warpred[t >> 5] = mx;
    __syncthreads();
    if (t == 0) {
        float r = warpred[0];
        #pragma unroll
        for (int w = 1; w < 8; w++) r = fmaxf(r, warpred[w]);
        bcast = r;
    }
    __syncthreads();
    mx = bcast;

    float sum = 0.0f;
    #pragma unroll
    for (int i = 0; i < 4; i++) { v[i] = expf(v[i] - mx); sum += v[i]; }
    __syncthreads();

    #pragma unroll
    for (int o = 16; o; o >>= 1) sum += __shfl_xor_sync(0xffffffffu, sum, o);
    if ((t & 31) == 0) warpred[t >> 5] = sum;
    __syncthreads();
    if (t == 0) {
        float r = 0.0f;
        #pragma unroll
        for (int w = 0; w < 8; w++) r += warpred[w];
        bcast = r;
    }
    __syncthreads();
    const float inv = 1.0f / bcast;

    #pragma unroll
    for (int i = 0; i < 4; i++)
        s[t + i * 256] = v[i] * inv;
}

// ---------------------------------------------------------------------------
extern "C" void kernel_launch(void* const* d_in, const int* in_sizes, int n_in,
                              void* d_out, int out_size)
{
    (void)in_sizes; (void)n_in; (void)out_size;
    const float*         k     = (const float*)d_in[0];          // [B, P, H]
    const float*         q     = (const float*)d_in[1];          // [B, Q, H]
    const unsigned char* qmask = (const unsigned char*)d_in[2];  // [B, Q] bool
    const float*         Wk    = (const float*)d_in[3];          // [H, H]
    const float*         Wq    = (const float*)d_in[4];          // [H, H]

    float* ctx    = (float*)d_out;                               // [B, P, H]
    float* alphas = ctx + (size_t)B_ * PLEN * HID;               // [B, P, Q]

    float *pkey, *qkey, *qT;
    cudaGetSymbolAddress((void**)&pkey, g_pkey);
    cudaGetSymbolAddress((void**)&qkey, g_qkey);
    cudaGetSymbolAddress((void**)&qT,   g_qT);

    static int smem_set = 0;
    if (!smem_set) {
        cudaFuncSetAttribute(gemm_3xbf16,
                             cudaFuncAttributeMaxDynamicSharedMemorySize, GSMEM);
        smem_set = 1;
    }

    // 0) qT[b] = q[b]^T
    transpose_q<<<dim3(QLEN / 32, HID / 32, B_), dim3(32, 8)>>>(q, qT);

    // 1) p_key = relu(k @ Wk^T)
    gemm_3xbf16<<<dim3(HID / 64, (B_ * PLEN) / 128, 1), NTHREADS, GSMEM>>>(
        k, Wk, pkey, HID, HID, 1, 0, 0, 0);

    // 2) q_key = relu(q @ Wq^T)
    gemm_3xbf16<<<dim3(HID / 64, (B_ * QLEN) / 128, 1), NTHREADS, GSMEM>>>(
        q, Wq, qkey, HID, HID, 1, 0, 0, 0);

    // 3) scores[b] = p_key[b] @ q_key[b]^T  -> raw into alphas region
    gemm_3xbf16<<<dim3(QLEN / 64, PLEN / 128, B_), NTHREADS, GSMEM>>>(
        pkey, qkey, alphas, HID, QLEN, 0,
        (size_t)PLEN * HID, (size_t)QLEN * HID, (size_t)PLEN * QLEN);

    // 4) softmax in place
    softmax_rows<<<B_ * PLEN, 256>>>(alphas, qmask);

    // 5) ctx[b] = alphas[b] @ q[b] == alphas[b] @ (qT[b])^T  (NT)
    gemm_3xbf16<<<dim3(HID / 64, PLEN / 128, B_), NTHREADS, GSMEM>>>(
        alphas, qT, ctx, QLEN, HID, 0,
        (size_t)PLEN * QLEN, (size_t)HID * QLEN, (size_t)PLEN * HID);
}